// round 1
// baseline (speedup 1.0000x reference)
#include <cuda_runtime.h>
#include <cuda_bf16.h>
#include <cstdint>
#include <cstddef>

// Problem constants (shapes are fixed by the dataset).
#define B_    256
#define DIN_  512
#define H_    1024
#define DOUT_ 512
#define T_    256

// ---------------------------------------------------------------------------
// Device scratch (static __device__ globals -- the sanctioned scratch path).
// hs buffer holds T+1 slabs of [B, H]: slab 0 = h0 (fcn latent), slab t+1 = h
// after GRU step t. Stored as split bf16 (hi + lo) so every GEMM consumer can
// run the 3-product split-bf16 path with ~2^-17 relative error.
// ---------------------------------------------------------------------------
__device__ __nv_bfloat16 g_hs_hi[(size_t)(T_ + 1) * B_ * H_];
__device__ __nv_bfloat16 g_hs_lo[(size_t)(T_ + 1) * B_ * H_];
__device__ __nv_bfloat16 g_Whi[6 * H_ * H_];   // rows: [w_ih(3H); w_hh(3H)] x H
__device__ __nv_bfloat16 g_Wlo[6 * H_ * H_];
__device__ __nv_bfloat16 g_xhi[B_ * DIN_],  g_xlo[B_ * DIN_];
__device__ __nv_bfloat16 g_w1hi[H_ * DIN_], g_w1lo[H_ * DIN_];
__device__ __nv_bfloat16 g_w2hi[H_ * H_],   g_w2lo[H_ * H_];
__device__ __nv_bfloat16 g_t1hi[B_ * H_],   g_t1lo[B_ * H_];
__device__ __nv_bfloat16 g_owhi[DOUT_ * H_], g_owlo[DOUT_ * H_];

// ---------------------------------------------------------------------------
// Split a fp32 tensor into bf16 hi + bf16 lo (exact residual split).
// "which" selects the destination device-global pair (avoids host-side
// cudaGetSymbolAddress entirely).
// ---------------------------------------------------------------------------
__global__ void split_kernel(int which, const float* __restrict__ src, int n) {
    int i = blockIdx.x * blockDim.x + threadIdx.x;
    if (i >= n) return;
    __nv_bfloat16 *hi, *lo;
    switch (which) {
        case 0: hi = g_xhi;  lo = g_xlo;  break;
        case 1: hi = g_w1hi; lo = g_w1lo; break;
        case 2: hi = g_w2hi; lo = g_w2lo; break;
        case 3: hi = g_Whi;              lo = g_Wlo;              break;
        case 4: hi = g_Whi + 3 * H_ * H_; lo = g_Wlo + 3 * H_ * H_; break;
        default: hi = g_owhi; lo = g_owlo; break;
    }
    float v = src[i];
    __nv_bfloat16 h = __float2bfloat16(v);
    hi[i] = h;
    lo[i] = __float2bfloat16(v - __bfloat162float(h));
}

// m16n8k16 bf16 MMA, fp32 accumulate in place.
__device__ __forceinline__ void mma_bf16(float* c,
                                         uint32_t a0, uint32_t a1, uint32_t a2, uint32_t a3,
                                         uint32_t b0, uint32_t b1) {
    asm volatile(
        "mma.sync.aligned.m16n8k16.row.col.f32.bf16.bf16.f32 "
        "{%0,%1,%2,%3}, {%4,%5,%6,%7}, {%8,%9}, {%0,%1,%2,%3};\n"
        : "+f"(c[0]), "+f"(c[1]), "+f"(c[2]), "+f"(c[3])
        : "r"(a0), "r"(a1), "r"(a2), "r"(a3), "r"(b0), "r"(b1));
}

__device__ __forceinline__ float sigm(float x) {
    return 1.0f / (1.0f + __expf(-x));
}
__device__ __forceinline__ float tanh_fast(float x) {
    float a = fabsf(x);
    float e = __expf(-2.0f * a);
    float t = (1.0f - e) / (1.0f + e);
    return copysignf(t, x);
}

// ---------------------------------------------------------------------------
// Generic split-bf16 GEMM:  C[M,N] = A[M,K] @ B[N,K]^T + bias[N]
// which: 0 -> A=x,  B=fcn_w1     (FCN layer 1)
//        1 -> A=t1, B=fcn_w2     (FCN layer 2)
//        2 -> A=hs(slabs 1..T), B=out_w  (output projection)
// mode:  0 -> split-write into g_t1hi/lo
//        1 -> write fp32 to outf (latent slice of d_out) AND split-write hs slab 0
//        2 -> permuted write: row m = t*B + b  ->  outf[b*T*N + t*N + n]
// BM=128, BN=64, BK=32; 256 threads (8 warps as 4m x 2n of 32x32 warp tiles).
// ---------------------------------------------------------------------------
__global__ __launch_bounds__(256) void gemm3_kernel(
    int which, const float* __restrict__ bias, float* __restrict__ outf,
    int M, int N, int K, int mode)
{
    const __nv_bfloat16 *Ahi, *Alo, *Bhi, *Blo;
    if (which == 0)      { Ahi = g_xhi;  Alo = g_xlo;  Bhi = g_w1hi; Blo = g_w1lo; }
    else if (which == 1) { Ahi = g_t1hi; Alo = g_t1lo; Bhi = g_w2hi; Blo = g_w2lo; }
    else                 { Ahi = g_hs_hi + (size_t)B_ * H_; Alo = g_hs_lo + (size_t)B_ * H_;
                           Bhi = g_owhi; Blo = g_owlo; }
    const uint32_t* A32h = (const uint32_t*)Ahi;
    const uint32_t* A32l = (const uint32_t*)Alo;
    const uint32_t* B32h = (const uint32_t*)Bhi;
    const uint32_t* B32l = (const uint32_t*)Blo;

    // Padded smem (row stride 20 u32 = 40 bf16): conflict-free for the
    // fragment access pattern (bank = 20*row + c, rows 0..7 map to distinct
    // bank groups 0,20,8,28,16,4,24,12 with c-spread < 4).
    __shared__ uint32_t sAh[128 * 20], sAl[128 * 20];
    __shared__ uint32_t sBh[64 * 20],  sBl[64 * 20];

    int tid  = threadIdx.x;
    int lane = tid & 31, warp = tid >> 5;
    int g = lane >> 2, t4 = lane & 3;
    int wm = warp >> 1, wn = warp & 1;
    int m0 = blockIdx.y * 128;
    int n0 = blockIdx.x * 64;
    int K2 = K >> 1;

    float acc[2][4][4];
#pragma unroll
    for (int a = 0; a < 2; a++)
#pragma unroll
        for (int b = 0; b < 4; b++)
#pragma unroll
            for (int c = 0; c < 4; c++) acc[a][b][c] = 0.0f;

    for (int k0 = 0; k0 < K; k0 += 32) {
        __syncthreads();
        int kc = k0 >> 1;
#pragma unroll
        for (int i = 0; i < 8; i++) {           // A tile: 128x16 u32
            int e = tid + i * 256;
            int r = e >> 4, c = e & 15;
            size_t gi = (size_t)(m0 + r) * K2 + kc + c;
            sAh[r * 20 + c] = A32h[gi];
            sAl[r * 20 + c] = A32l[gi];
        }
#pragma unroll
        for (int i = 0; i < 4; i++) {           // B tile: 64x16 u32
            int e = tid + i * 256;
            int r = e >> 4, c = e & 15;
            size_t gi = (size_t)(n0 + r) * K2 + kc + c;
            sBh[r * 20 + c] = B32h[gi];
            sBl[r * 20 + c] = B32l[gi];
        }
        __syncthreads();

#pragma unroll
        for (int kk = 0; kk < 2; kk++) {        // two k16 chunks per tile
            int base = kk * 8 + t4;
            uint32_t ah[2][4], al[2][4], bh[4][2], bl[4][2];
#pragma unroll
            for (int mf = 0; mf < 2; mf++) {
                int rb = wm * 32 + mf * 16;
                ah[mf][0] = sAh[(rb + g) * 20 + base];
                ah[mf][1] = sAh[(rb + g + 8) * 20 + base];
                ah[mf][2] = sAh[(rb + g) * 20 + base + 4];
                ah[mf][3] = sAh[(rb + g + 8) * 20 + base + 4];
                al[mf][0] = sAl[(rb + g) * 20 + base];
                al[mf][1] = sAl[(rb + g + 8) * 20 + base];
                al[mf][2] = sAl[(rb + g) * 20 + base + 4];
                al[mf][3] = sAl[(rb + g + 8) * 20 + base + 4];
            }
#pragma unroll
            for (int nf = 0; nf < 4; nf++) {
                int nb = wn * 32 + nf * 8 + g;
                bh[nf][0] = sBh[nb * 20 + base];
                bh[nf][1] = sBh[nb * 20 + base + 4];
                bl[nf][0] = sBl[nb * 20 + base];
                bl[nf][1] = sBl[nb * 20 + base + 4];
            }
#pragma unroll
            for (int mf = 0; mf < 2; mf++)
#pragma unroll
                for (int nf = 0; nf < 4; nf++) {
                    mma_bf16(acc[mf][nf], ah[mf][0], ah[mf][1], ah[mf][2], ah[mf][3],
                             bh[nf][0], bh[nf][1]);
                    mma_bf16(acc[mf][nf], ah[mf][0], ah[mf][1], ah[mf][2], ah[mf][3],
                             bl[nf][0], bl[nf][1]);
                    mma_bf16(acc[mf][nf], al[mf][0], al[mf][1], al[mf][2], al[mf][3],
                             bh[nf][0], bh[nf][1]);
                }
        }
    }

    // Epilogue
#pragma unroll
    for (int mf = 0; mf < 2; mf++)
#pragma unroll
        for (int nf = 0; nf < 4; nf++)
#pragma unroll
            for (int rr = 0; rr < 2; rr++)
#pragma unroll
                for (int cc = 0; cc < 2; cc++) {
                    int row = m0 + wm * 32 + mf * 16 + g + rr * 8;
                    int col = n0 + wn * 32 + nf * 8 + 2 * t4 + cc;
                    float v = acc[mf][nf][rr * 2 + cc] + bias[col];
                    if (mode == 0) {
                        __nv_bfloat16 h = __float2bfloat16(v);
                        g_t1hi[(size_t)row * N + col] = h;
                        g_t1lo[(size_t)row * N + col] =
                            __float2bfloat16(v - __bfloat162float(h));
                    } else if (mode == 1) {
                        outf[(size_t)row * N + col] = v;     // latent slice of d_out
                        __nv_bfloat16 h = __float2bfloat16(v);
                        g_hs_hi[(size_t)row * N + col] = h;  // slab 0 = h0
                        g_hs_lo[(size_t)row * N + col] =
                            __float2bfloat16(v - __bfloat162float(h));
                    } else {
                        int t = row >> 8;          // row = t*B + b, B = 256
                        int b = row & 255;
                        int Trt = M >> 8;
                        outf[(size_t)b * Trt * N + (size_t)t * N + col] = v;
                    }
                }
}

// ---------------------------------------------------------------------------
// Fused GRU step, split-bf16 tensor cores.
// Per CTA: 128 batch rows x 16 hidden columns, all 6 gate blocks.
// Grid (64 j-tiles, 2 m-tiles), 256 threads (8 warps, 16 rows each).
// Reads h_t from hs slab t, writes h_{t+1} split into hs slab t+1.
// ---------------------------------------------------------------------------
__global__ __launch_bounds__(256) void gru_kernel(
    int t, const float* __restrict__ b_ih, const float* __restrict__ b_hh)
{
    __shared__ uint32_t sAh[128 * 20], sAl[128 * 20];
    __shared__ uint32_t sBh[96 * 20],  sBl[96 * 20];

    int tid  = threadIdx.x;
    int lane = tid & 31, warp = tid >> 5;
    int g = lane >> 2, t4 = lane & 3;
    int m0 = blockIdx.y * 128;
    int j0 = blockIdx.x * 16;

    const uint32_t* Hh = (const uint32_t*)g_hs_hi + (size_t)t * (B_ * H_ / 2);
    const uint32_t* Hl = (const uint32_t*)g_hs_lo + (size_t)t * (B_ * H_ / 2);
    const uint32_t* W32h = (const uint32_t*)g_Whi;
    const uint32_t* W32l = (const uint32_t*)g_Wlo;

    float acc[6][2][4];
#pragma unroll
    for (int a = 0; a < 6; a++)
#pragma unroll
        for (int b = 0; b < 2; b++)
#pragma unroll
            for (int c = 0; c < 4; c++) acc[a][b][c] = 0.0f;

    for (int k0 = 0; k0 < H_; k0 += 32) {
        __syncthreads();
        int kc = k0 >> 1;
#pragma unroll
        for (int i = 0; i < 8; i++) {           // A (h) tile: 128x16 u32
            int e = tid + i * 256;
            int r = e >> 4, c = e & 15;
            size_t gi = (size_t)(m0 + r) * (H_ / 2) + kc + c;
            sAh[r * 20 + c] = Hh[gi];
            sAl[r * 20 + c] = Hl[gi];
        }
#pragma unroll
        for (int i = 0; i < 6; i++) {           // W tile: 96 rows (6 gates x 16 j)
            int e = tid + i * 256;
            int r = e >> 4, c = e & 15;
            int gate = r >> 4, rj = r & 15;
            size_t wrow = (size_t)gate * H_ + j0 + rj;
            size_t gi = wrow * (H_ / 2) + kc + c;
            sBh[r * 20 + c] = W32h[gi];
            sBl[r * 20 + c] = W32l[gi];
        }
        __syncthreads();

#pragma unroll
        for (int kk = 0; kk < 2; kk++) {
            int base = kk * 8 + t4;
            int rb = warp * 16;
            uint32_t ah[4], al[4];
            ah[0] = sAh[(rb + g) * 20 + base];
            ah[1] = sAh[(rb + g + 8) * 20 + base];
            ah[2] = sAh[(rb + g) * 20 + base + 4];
            ah[3] = sAh[(rb + g + 8) * 20 + base + 4];
            al[0] = sAl[(rb + g) * 20 + base];
            al[1] = sAl[(rb + g + 8) * 20 + base];
            al[2] = sAl[(rb + g) * 20 + base + 4];
            al[3] = sAl[(rb + g + 8) * 20 + base + 4];
#pragma unroll
            for (int gate = 0; gate < 6; gate++) {
#pragma unroll
                for (int nf = 0; nf < 2; nf++) {
                    int nb = gate * 16 + nf * 8 + g;
                    uint32_t b0h = sBh[nb * 20 + base];
                    uint32_t b1h = sBh[nb * 20 + base + 4];
                    uint32_t b0l = sBl[nb * 20 + base];
                    uint32_t b1l = sBl[nb * 20 + base + 4];
                    mma_bf16(acc[gate][nf], ah[0], ah[1], ah[2], ah[3], b0h, b1h);
                    mma_bf16(acc[gate][nf], ah[0], ah[1], ah[2], ah[3], b0l, b1l);
                    mma_bf16(acc[gate][nf], al[0], al[1], al[2], al[3], b0h, b1h);
                }
            }
        }
    }

    // Epilogue: gate math + state update, split-write h_{t+1}.
    const __nv_bfloat16* src_hi = g_hs_hi + (size_t)t * B_ * H_;
    const __nv_bfloat16* src_lo = g_hs_lo + (size_t)t * B_ * H_;
    __nv_bfloat16* dst_hi = g_hs_hi + (size_t)(t + 1) * B_ * H_;
    __nv_bfloat16* dst_lo = g_hs_lo + (size_t)(t + 1) * B_ * H_;

#pragma unroll
    for (int nf = 0; nf < 2; nf++)
#pragma unroll
        for (int cc = 0; cc < 2; cc++) {
            int j = j0 + nf * 8 + 2 * t4 + cc;
            float bir = b_ih[j], biz = b_ih[H_ + j], bin = b_ih[2 * H_ + j];
            float bhr = b_hh[j], bhz = b_hh[H_ + j], bhn = b_hh[2 * H_ + j];
#pragma unroll
            for (int rr = 0; rr < 2; rr++) {
                int m  = m0 + warp * 16 + g + rr * 8;
                int ci = rr * 2 + cc;
                float ir  = acc[0][nf][ci] + bir;
                float iz  = acc[1][nf][ci] + biz;
                float inn = acc[2][nf][ci] + bin;
                float hr  = acc[3][nf][ci] + bhr;
                float hz  = acc[4][nf][ci] + bhz;
                float hn  = acc[5][nf][ci] + bhn;
                float r  = sigm(ir + hr);
                float z  = sigm(iz + hz);
                float nn = tanh_fast(inn + r * hn);
                size_t idx = (size_t)m * H_ + j;
                float hold = __bfloat162float(src_hi[idx]) + __bfloat162float(src_lo[idx]);
                float hnew = (1.0f - z) * nn + z * hold;
                __nv_bfloat16 hh = __float2bfloat16(hnew);
                dst_hi[idx] = hh;
                dst_lo[idx] = __float2bfloat16(hnew - __bfloat162float(hh));
            }
        }
}

// ---------------------------------------------------------------------------
// Host launcher: graph-capturable (kernel launches only, no allocations,
// no syncs, no device reads). T derived from out_size, not from d_in.
// ---------------------------------------------------------------------------
extern "C" void kernel_launch(void* const* d_in, const int* in_sizes, int n_in,
                              void* d_out, int out_size) {
    const float* x     = (const float*)d_in[0];
    const float* w1    = (const float*)d_in[1];
    const float* b1    = (const float*)d_in[2];
    const float* w2    = (const float*)d_in[3];
    const float* b2    = (const float*)d_in[4];
    const float* w_ih  = (const float*)d_in[5];
    const float* b_ih  = (const float*)d_in[6];
    const float* w_hh  = (const float*)d_in[7];
    const float* b_hh  = (const float*)d_in[8];
    const float* out_w = (const float*)d_in[9];
    const float* out_b = (const float*)d_in[10];
    float* out = (float*)d_out;

    int T = (out_size - B_ * H_) / (B_ * DOUT_);   // = 256
    if (T > T_) T = T_;

    // Split fp32 inputs into bf16 hi/lo
    split_kernel<<<(B_ * DIN_ + 255) / 256, 256>>>(0, x, B_ * DIN_);
    split_kernel<<<(H_ * DIN_ + 255) / 256, 256>>>(1, w1, H_ * DIN_);
    split_kernel<<<(H_ * H_ + 255) / 256, 256>>>(2, w2, H_ * H_);
    split_kernel<<<(3 * H_ * H_ + 255) / 256, 256>>>(3, w_ih, 3 * H_ * H_);
    split_kernel<<<(3 * H_ * H_ + 255) / 256, 256>>>(4, w_hh, 3 * H_ * H_);
    split_kernel<<<(DOUT_ * H_ + 255) / 256, 256>>>(5, out_w, DOUT_ * H_);

    // FCN layer 1: t1 = x @ w1^T + b1   (M=256, N=1024, K=512)
    gemm3_kernel<<<dim3(H_ / 64, B_ / 128), 256>>>(0, b1, nullptr,
                                                   B_, H_, DIN_, 0);
    // FCN layer 2: latent = t1 @ w2^T + b2  -> d_out latent slice + hs slab 0
    gemm3_kernel<<<dim3(H_ / 64, B_ / 128), 256>>>(
        1, b2, out + (size_t)B_ * T * DOUT_, B_, H_, H_, 1);

    // GRU recurrence
    for (int t = 0; t < T; t++)
        gru_kernel<<<dim3(H_ / 16, B_ / 128), 256>>>(t, b_ih, b_hh);

    // Output projection: recon[b,t,:] = hs[t,b,:] @ out_w^T + out_b
    gemm3_kernel<<<dim3(DOUT_ / 64, (T * B_) / 128), 256>>>(
        2, out_b, out, T * B_, DOUT_, H_, 2);
}